// round 9
// baseline (speedup 1.0000x reference)
#include <cuda_runtime.h>
#include <cuda_bf16.h>
#include <cstdint>

// NCE loss (training branch, size_average=True).
// N=4096, E=1024, V=50257, K=25.
// Persistent kernel, 1184 CTAs (8/SM). Fully warp-autonomous mainloop:
// each CTA's (row, k) dot list is flattened and strided by warp, so warps
// free-run with NO barriers and NO smem staging. x is read via __ldg and
// stays L1-resident (8 warps reuse each row); the weight gather uses __ldcg
// so the 436MB weight stream does not evict x from L1.

#define THREADS 256
#define NWARP   8
#define GRID    1184          // 148 SMs * 8 CTAs

__global__ __launch_bounds__(THREADS, 8)
void nce_main(const float* __restrict__ x,
              const int*   __restrict__ target,
              const int*   __restrict__ noise_idx,
              const float* __restrict__ weight,
              const float* __restrict__ bias,
              const float* __restrict__ noise,
              float* __restrict__ out,
              int N, int E, int K)
{
    const int tid  = threadIdx.x;
    const int lane = tid & 31;
    const int wid  = tid >> 5;
    const int nk   = K + 1;                       // 26

    __shared__ float wloss[NWARP];

    const int n0 = blockIdx.x;
    // rows handled by this CTA: n0, n0+GRID, ... ; flattened dot count
    const int nrows = (n0 < N) ? ((N - 1 - n0) / GRID + 1) : 0;
    const int ndots = nrows * nk;

    float loss = 0.0f;                            // lane-0-held accumulator

    for (int d = wid; d < ndots; d += NWARP) {
        const int r = d / 26;                     // const divisor -> mul/shift
        const int k = d - r * 26;
        const int n = n0 + r * GRID;

        const int idx = (k == 0) ? __ldg(&target[n])
                                 : __ldg(&noise_idx[n * K + (k - 1)]);
        const float4* wrow = reinterpret_cast<const float4*>(weight + (size_t)idx * E);
        const float4* xrow = reinterpret_cast<const float4*>(x + (size_t)n * E);

        float s = 0.0f;
        #pragma unroll
        for (int j = 0; j < 8; j++) {
            const float4 wv = __ldcg(&wrow[lane + 32 * j]);   // L2-only stream
            const float4 xv = __ldg (&xrow[lane + 32 * j]);   // L1-resident
            s += wv.x * xv.x + wv.y * xv.y + wv.z * xv.z + wv.w * xv.w;
        }
        #pragma unroll
        for (int o = 16; o; o >>= 1)
            s += __shfl_xor_sync(0xffffffffu, s, o);

        if (lane == 0) {
            const float logit = s + __ldg(&bias[idx]);
            const float p     = __expf(logit - 9.0f);
            const float kpn   = 25.0f * __ldg(&noise[idx]);
            const float num   = (k == 0) ? p : kpn;
            loss += __logf(num / (p + kpn));
        }
    }

    if (lane == 0) wloss[wid] = loss;
    __syncthreads();
    if (tid == 0) {
        float t = 0.0f;
        #pragma unroll
        for (int w = 0; w < NWARP; w++) t += wloss[w];
        atomicAdd(out, -t / (float)N);            // one atomic per CTA
    }
}

extern "C" void kernel_launch(void* const* d_in, const int* in_sizes, int n_in,
                              void* d_out, int out_size)
{
    const float* x         = (const float*)d_in[0];
    const int*   target    = (const int*)  d_in[1];
    const int*   noise_idx = (const int*)  d_in[2];
    const float* weight    = (const float*)d_in[3];
    const float* bias      = (const float*)d_in[4];
    const float* noise     = (const float*)d_in[5];

    const int N = in_sizes[1];            // 4096
    const int E = in_sizes[0] / N;        // 1024
    const int K = in_sizes[2] / N;        // 25

    cudaMemsetAsync(d_out, 0, sizeof(float));
    nce_main<<<GRID, THREADS>>>(x, target, noise_idx, weight, bias, noise,
                                (float*)d_out, N, E, K);
}